// round 1
// baseline (speedup 1.0000x reference)
#include <cuda_runtime.h>

// LDE_58961311040249 — fused two-GEMM formulation.
//   d[b,t,k]  = s[k] * (||x_bt||^2 - 2 x_bt·m_k + ||m_k||^2)
//   w         = softmax_k(d)
//   out[b,k,i]= (sum_t w*x_i)/T - m[i,k]*(sum_t w)/T
//
// Kernel 1: per (batch, T-chunk) CTA — GEMM1 + softmax + GEMM2, partials to
//           __device__ scratch (deterministic, no atomics).
// Kernel 2: reduce partials, apply m*wsum correction, write d_out.

#define B_      16
#define T_      2048
#define NIN     128
#define NOUT    64
#define CHUNKS  16
#define TILE_T  (T_ / CHUNKS)   // 128

#define XS_LD   132   // padded row stride (floats), 16B-aligned, bank-spread
#define MS_LD   132
#define WS_LD   68

__device__ float g_partE [B_ * CHUNKS * NOUT * NIN];  // 8 MB scratch
__device__ float g_partWS[B_ * CHUNKS * NOUT];

__global__ __launch_bounds__(256) void lde_phase1(
    const float* __restrict__ x,
    const float* __restrict__ s,
    const float* __restrict__ m)
{
    extern __shared__ float sm[];
    float* x_s = sm;                         // TILE_T * XS_LD
    float* m_s = x_s + TILE_T * XS_LD;       // NOUT * MS_LD   (codeword-major)
    float* w_s = m_s + NOUT * MS_LD;         // TILE_T * WS_LD
    float* xn  = w_s + TILE_T * WS_LD;       // TILE_T
    float* mn  = xn + TILE_T;                // NOUT
    float* s_s = mn + NOUT;                  // NOUT

    const int tid = threadIdx.x;
    const int c   = blockIdx.x;
    const int b   = blockIdx.y;
    const float* xg = x + ((size_t)b * T_ + (size_t)c * TILE_T) * NIN;

    // ---- load M (transpose to [k][i]) ----
    for (int e = tid; e < NIN * NOUT; e += 256) {
        int i = e >> 6, k = e & 63;          // m[i,k] at i*64+k
        m_s[k * MS_LD + i] = m[e];
    }
    // ---- load X tile (float4, coalesced) ----
    for (int e = tid; e < TILE_T * (NIN / 4); e += 256) {
        int r = e >> 5, i4 = e & 31;
        float4 v = reinterpret_cast<const float4*>(xg)[r * (NIN / 4) + i4];
        reinterpret_cast<float4*>(x_s + r * XS_LD)[i4] = v;
    }
    __syncthreads();

    // ---- row norms ----
    if (tid < TILE_T) {
        const float* row = x_s + tid * XS_LD;
        float acc = 0.f;
        #pragma unroll
        for (int i = 0; i < NIN; i++) acc += row[i] * row[i];
        xn[tid] = acc;
    }
    if (tid < NOUT) {
        const float* row = m_s + tid * MS_LD;
        float acc = 0.f;
        #pragma unroll
        for (int i = 0; i < NIN; i++) acc += row[i] * row[i];
        mn[tid]  = acc;
        s_s[tid] = s[tid];
    }
    __syncthreads();

    // ======== GEMM1: dot[r][k] = x_r · m_k  (128x64, micro 8x4) ========
    const int tx = tid & 15, ty = tid >> 4;
    const int r0 = ty * 8, k0 = tx * 4;
    float acc[8][4];
    #pragma unroll
    for (int u = 0; u < 8; u++)
        #pragma unroll
        for (int v = 0; v < 4; v++) acc[u][v] = 0.f;

    for (int kk = 0; kk < NIN; kk += 4) {
        float4 a[8], bb[4];
        #pragma unroll
        for (int u = 0; u < 8; u++)
            a[u] = *reinterpret_cast<const float4*>(x_s + (r0 + u) * XS_LD + kk);
        #pragma unroll
        for (int v = 0; v < 4; v++)
            bb[v] = *reinterpret_cast<const float4*>(m_s + (k0 + v) * MS_LD + kk);
        #pragma unroll
        for (int u = 0; u < 8; u++)
            #pragma unroll
            for (int v = 0; v < 4; v++)
                acc[u][v] += a[u].x * bb[v].x + a[u].y * bb[v].y +
                             a[u].z * bb[v].z + a[u].w * bb[v].w;
    }

    // ======== d-transform + softmax over k (16-lane shuffle groups) ========
    #pragma unroll
    for (int u = 0; u < 8; u++) {
        const int r  = r0 + u;
        const float xr = xn[r];
        float dv[4];
        #pragma unroll
        for (int v = 0; v < 4; v++)
            dv[v] = s_s[k0 + v] * (xr - 2.f * acc[u][v] + mn[k0 + v]);

        float mx = fmaxf(fmaxf(dv[0], dv[1]), fmaxf(dv[2], dv[3]));
        #pragma unroll
        for (int off = 1; off < 16; off <<= 1)
            mx = fmaxf(mx, __shfl_xor_sync(0xffffffffu, mx, off));

        float ev[4], ssum = 0.f;
        #pragma unroll
        for (int v = 0; v < 4; v++) { ev[v] = __expf(dv[v] - mx); ssum += ev[v]; }
        #pragma unroll
        for (int off = 1; off < 16; off <<= 1)
            ssum += __shfl_xor_sync(0xffffffffu, ssum, off);

        const float inv = 1.f / ssum;
        #pragma unroll
        for (int v = 0; v < 4; v++)
            w_s[r * WS_LD + k0 + v] = ev[v] * inv;
    }
    __syncthreads();

    // ======== GEMM2: E[k][i] = sum_r w[r][k] * x[r][i]  (64x128, micro 4x8) ====
    const int ix = tid & 15, ky = tid >> 4;
    const int i0 = ix * 8, kb = ky * 4;
    float acc2[4][8];
    #pragma unroll
    for (int kv = 0; kv < 4; kv++)
        #pragma unroll
        for (int iv = 0; iv < 8; iv++) acc2[kv][iv] = 0.f;

    for (int r = 0; r < TILE_T; r++) {
        float4 wv = *reinterpret_cast<const float4*>(w_s + r * WS_LD + kb);
        float4 xa = *reinterpret_cast<const float4*>(x_s + r * XS_LD + i0);
        float4 xb = *reinterpret_cast<const float4*>(x_s + r * XS_LD + i0 + 4);
        float wk[4] = {wv.x, wv.y, wv.z, wv.w};
        #pragma unroll
        for (int kv = 0; kv < 4; kv++) {
            acc2[kv][0] += wk[kv] * xa.x;  acc2[kv][1] += wk[kv] * xa.y;
            acc2[kv][2] += wk[kv] * xa.z;  acc2[kv][3] += wk[kv] * xa.w;
            acc2[kv][4] += wk[kv] * xb.x;  acc2[kv][5] += wk[kv] * xb.y;
            acc2[kv][6] += wk[kv] * xb.z;  acc2[kv][7] += wk[kv] * xb.w;
        }
    }

    float* pe = g_partE + (size_t)(b * CHUNKS + c) * NOUT * NIN;
    #pragma unroll
    for (int kv = 0; kv < 4; kv++) {
        float4 o0 = make_float4(acc2[kv][0], acc2[kv][1], acc2[kv][2], acc2[kv][3]);
        float4 o1 = make_float4(acc2[kv][4], acc2[kv][5], acc2[kv][6], acc2[kv][7]);
        *reinterpret_cast<float4*>(pe + (kb + kv) * NIN + i0)     = o0;
        *reinterpret_cast<float4*>(pe + (kb + kv) * NIN + i0 + 4) = o1;
    }

    // ---- per-chunk wsum[k] ----
    if (tid < NOUT) {
        float a = 0.f;
        #pragma unroll 8
        for (int r = 0; r < TILE_T; r++) a += w_s[r * WS_LD + tid];
        g_partWS[(b * CHUNKS + c) * NOUT + tid] = a;
    }
}

__global__ __launch_bounds__(256) void lde_phase2(
    const float* __restrict__ m, float* __restrict__ out)
{
    const int g = blockIdx.x * 256 + threadIdx.x;    // b*8192 + k*128 + i
    const int b = g >> 13;
    const int k = (g >> 7) & 63;
    const int i = g & 127;

    float se = 0.f, sw = 0.f;
    #pragma unroll
    for (int c = 0; c < CHUNKS; c++) {
        se += g_partE[((size_t)(b * CHUNKS + c) * NOUT + k) * NIN + i];
        sw += g_partWS[(b * CHUNKS + c) * NOUT + k];
    }
    out[g] = (se - m[i * NOUT + k] * sw) * (1.f / (float)T_);
}

extern "C" void kernel_launch(void* const* d_in, const int* in_sizes, int n_in,
                              void* d_out, int out_size)
{
    // map inputs by element count (robust to ordering): x=4194304, s=64, m=8192
    const float* x = nullptr; const float* s = nullptr; const float* m = nullptr;
    for (int i = 0; i < n_in; i++) {
        if      (in_sizes[i] == B_ * T_ * NIN) x = (const float*)d_in[i];
        else if (in_sizes[i] == NOUT)          s = (const float*)d_in[i];
        else if (in_sizes[i] == NIN * NOUT)    m = (const float*)d_in[i];
    }
    float* out = (float*)d_out;

    const int smem_bytes =
        (TILE_T * XS_LD + NOUT * MS_LD + TILE_T * WS_LD + TILE_T + 2 * NOUT)
        * (int)sizeof(float);   // 137,216 B

    cudaFuncSetAttribute(lde_phase1,
                         cudaFuncAttributeMaxDynamicSharedMemorySize, smem_bytes);

    lde_phase1<<<dim3(CHUNKS, B_), 256, smem_bytes>>>(x, s, m);
    lde_phase2<<<(B_ * NOUT * NIN) / 256, 256>>>(m, out);
}

// round 2
// speedup vs baseline: 1.0237x; 1.0237x over previous
#include <cuda_runtime.h>

// LDE_58961311040249 — fused two-GEMM formulation, f32x2 packed math (R2).
//   d[b,t,k]  = s[k] * (||x_bt||^2 - 2 x_bt·m_k + ||m_k||^2)
//   w         = softmax_k(d)
//   out[b,k,i]= (sum_t w*x_i)/T - m[i,k]*(sum_t w)/T

#define B_      16
#define T_      2048
#define NIN     128
#define NOUT    64
#define CHUNKS  16
#define TILE_T  (T_ / CHUNKS)   // 128

#define XS_LD   132   // x row stride (floats)
#define MS_LD   132   // m row stride (floats)
#define WS2_LD  66    // w2 row stride (u64 pairs)

__device__ float g_partE [B_ * CHUNKS * NOUT * NIN];  // 8 MB scratch
__device__ float g_partWS[B_ * CHUNKS * NOUT];

typedef unsigned long long u64;

__device__ __forceinline__ void lds_v2(u64 &p0, u64 &p1, unsigned smem_off) {
    asm volatile("ld.shared.v2.u64 {%0,%1}, [%2];"
                 : "=l"(p0), "=l"(p1) : "r"(smem_off));
}
__device__ __forceinline__ void fma2(u64 &d, u64 a, u64 b) {
    asm("fma.rn.f32x2 %0, %1, %2, %0;" : "+l"(d) : "l"(a), "l"(b));
}
__device__ __forceinline__ u64 pack2(float lo, float hi) {
    u64 d; asm("mov.b64 %0, {%1,%2};" : "=l"(d) : "f"(lo), "f"(hi)); return d;
}
__device__ __forceinline__ float2 unpack2(u64 v) {
    float2 r; asm("mov.b64 {%0,%1}, %2;" : "=f"(r.x), "=f"(r.y) : "l"(v)); return r;
}

__global__ __launch_bounds__(256) void lde_phase1(
    const float* __restrict__ x,
    const float* __restrict__ s,
    const float* __restrict__ m)
{
    extern __shared__ float smf[];
    float* x_s = smf;                                   // 128*132 f
    float* m_s = x_s + TILE_T * XS_LD;                  // 64*132 f
    u64*   w2  = (u64*)(m_s + NOUT * MS_LD);            // 128*66 u64, (w,w) pairs
    float* xn  = (float*)(w2 + TILE_T * WS2_LD);        // 128
    float* mn  = xn + TILE_T;                           // 64
    float* s_s = mn + NOUT;                             // 64

    const int tid = threadIdx.x;
    const int c   = blockIdx.x;
    const int b   = blockIdx.y;
    const float* xg = x + ((size_t)b * T_ + (size_t)c * TILE_T) * NIN;

    // ---- load M (transpose to [k][i]) ----
    for (int e = tid; e < NIN * NOUT; e += 256) {
        int i = e >> 6, k = e & 63;
        m_s[k * MS_LD + i] = m[e];
    }
    // ---- load X tile ----
    for (int e = tid; e < TILE_T * (NIN / 4); e += 256) {
        int r = e >> 5, i4 = e & 31;
        float4 v = reinterpret_cast<const float4*>(xg)[r * (NIN / 4) + i4];
        reinterpret_cast<float4*>(x_s + r * XS_LD)[i4] = v;
    }
    __syncthreads();

    // ---- row norms ----
    if (tid < TILE_T) {
        const float* row = x_s + tid * XS_LD;
        float acc = 0.f;
        #pragma unroll
        for (int i = 0; i < NIN; i++) acc += row[i] * row[i];
        xn[tid] = acc;
    }
    if (tid < NOUT) {
        const float* row = m_s + tid * MS_LD;
        float acc = 0.f;
        #pragma unroll
        for (int i = 0; i < NIN; i++) acc += row[i] * row[i];
        mn[tid]  = acc;
        s_s[tid] = s[tid];
    }
    __syncthreads();

    const unsigned xb = (unsigned)__cvta_generic_to_shared(x_s);
    const unsigned mb = (unsigned)__cvta_generic_to_shared(m_s);
    const unsigned wbse = (unsigned)__cvta_generic_to_shared(w2);

    // ======== GEMM1: dot[r][k] = x_r · m_k  (128x64, micro 8x4, f32x2) ======
    const int tx = tid & 15, ty = tid >> 4;
    const int r0 = ty * 8, k0 = tx * 4;
    u64 accp[8][4];
    #pragma unroll
    for (int u = 0; u < 8; u++)
        #pragma unroll
        for (int v = 0; v < 4; v++) accp[u][v] = 0ull;

    const unsigned ax = xb + (unsigned)(r0 * XS_LD) * 4u;
    const unsigned bx = mb + (unsigned)(k0 * MS_LD) * 4u;

    #pragma unroll 2
    for (int kk = 0; kk < NIN; kk += 4) {
        u64 a0[8], a1[8], b0[4], b1[4];
        #pragma unroll
        for (int u = 0; u < 8; u++)
            lds_v2(a0[u], a1[u], ax + (unsigned)(u * XS_LD + kk) * 4u);
        #pragma unroll
        for (int v = 0; v < 4; v++)
            lds_v2(b0[v], b1[v], bx + (unsigned)(v * MS_LD + kk) * 4u);
        #pragma unroll
        for (int u = 0; u < 8; u++)
            #pragma unroll
            for (int v = 0; v < 4; v++) {
                fma2(accp[u][v], a0[u], b0[v]);
                fma2(accp[u][v], a1[u], b1[v]);
            }
    }

    // ======== d-transform + softmax over k (16-lane shuffle groups) ========
    #pragma unroll
    for (int u = 0; u < 8; u++) {
        const int r  = r0 + u;
        const float xr = xn[r];
        float dv[4];
        #pragma unroll
        for (int v = 0; v < 4; v++) {
            float2 p = unpack2(accp[u][v]);
            float dot = p.x + p.y;
            dv[v] = s_s[k0 + v] * (xr - 2.f * dot + mn[k0 + v]);
        }
        float mx = fmaxf(fmaxf(dv[0], dv[1]), fmaxf(dv[2], dv[3]));
        #pragma unroll
        for (int off = 1; off < 16; off <<= 1)
            mx = fmaxf(mx, __shfl_xor_sync(0xffffffffu, mx, off));

        float ev[4], ssum = 0.f;
        #pragma unroll
        for (int v = 0; v < 4; v++) { ev[v] = __expf(dv[v] - mx); ssum += ev[v]; }
        #pragma unroll
        for (int off = 1; off < 16; off <<= 1)
            ssum += __shfl_xor_sync(0xffffffffu, ssum, off);

        const float inv = 1.f / ssum;
        #pragma unroll
        for (int v = 0; v < 4; v++) {
            float wv = ev[v] * inv;
            w2[r * WS2_LD + k0 + v] = pack2(wv, wv);   // pre-duplicated pair
        }
    }
    __syncthreads();

    // ======== GEMM2: E[k][i] = sum_r w[r][k]*x[r][i] (64x128, 4x8, f32x2) ===
    const int ix = tid & 15, ky = tid >> 4;
    const int i0 = ix * 8, kb = ky * 4;
    u64 acc2p[4][4];   // [kv][iv-pair]; pair = outputs (i0+2j, i0+2j+1)
    #pragma unroll
    for (int kv = 0; kv < 4; kv++)
        #pragma unroll
        for (int j = 0; j < 4; j++) acc2p[kv][j] = 0ull;

    const unsigned wadr = wbse + (unsigned)kb * 8u;
    const unsigned xadr = xb + (unsigned)i0 * 4u;

    #pragma unroll 4
    for (int r = 0; r < TILE_T; r++) {
        u64 wp[4], xp[4];
        lds_v2(wp[0], wp[1], wadr + (unsigned)(r * WS2_LD) * 8u);
        lds_v2(wp[2], wp[3], wadr + (unsigned)(r * WS2_LD) * 8u + 16u);
        lds_v2(xp[0], xp[1], xadr + (unsigned)(r * XS_LD) * 4u);
        lds_v2(xp[2], xp[3], xadr + (unsigned)(r * XS_LD) * 4u + 16u);
        #pragma unroll
        for (int kv = 0; kv < 4; kv++)
            #pragma unroll
            for (int j = 0; j < 4; j++)
                fma2(acc2p[kv][j], wp[kv], xp[j]);
    }

    float* pe = g_partE + (size_t)(b * CHUNKS + c) * NOUT * NIN;
    #pragma unroll
    for (int kv = 0; kv < 4; kv++)
        #pragma unroll
        for (int j = 0; j < 4; j++)
            *reinterpret_cast<u64*>(pe + (kb + kv) * NIN + i0 + 2 * j) = acc2p[kv][j];

    // ---- per-chunk wsum[k] ----
    if (tid < NOUT) {
        const float* wf = (const float*)w2;
        float a = 0.f;
        #pragma unroll 8
        for (int r = 0; r < TILE_T; r++) a += wf[(r * WS2_LD + tid) * 2];
        g_partWS[(b * CHUNKS + c) * NOUT + tid] = a;
    }
}

__global__ __launch_bounds__(256) void lde_phase2(
    const float* __restrict__ m, float* __restrict__ out)
{
    const int g4 = blockIdx.x * 256 + threadIdx.x;   // 32768 float4 slots
    const int b  = g4 >> 11;          // 2048 float4 per batch
    const int k  = (g4 >> 5) & 63;
    const int i0 = (g4 & 31) * 4;

    float4 se = make_float4(0.f, 0.f, 0.f, 0.f);
    float  sw = 0.f;
    #pragma unroll
    for (int c = 0; c < CHUNKS; c++) {
        const float4 v = *reinterpret_cast<const float4*>(
            g_partE + ((size_t)(b * CHUNKS + c) * NOUT + k) * NIN + i0);
        se.x += v.x; se.y += v.y; se.z += v.z; se.w += v.w;
        sw   += g_partWS[(b * CHUNKS + c) * NOUT + k];
    }
    const float inv_t = 1.f / (float)T_;
    float4 o;
    o.x = (se.x - m[(i0 + 0) * NOUT + k] * sw) * inv_t;
    o.y = (se.y - m[(i0 + 1) * NOUT + k] * sw) * inv_t;
    o.z = (se.z - m[(i0 + 2) * NOUT + k] * sw) * inv_t;
    o.w = (se.w - m[(i0 + 3) * NOUT + k] * sw) * inv_t;
    *reinterpret_cast<float4*>(out + ((size_t)b * NOUT + k) * NIN + i0) = o;
}

extern "C" void kernel_launch(void* const* d_in, const int* in_sizes, int n_in,
                              void* d_out, int out_size)
{
    const float* x = nullptr; const float* s = nullptr; const float* m = nullptr;
    for (int i = 0; i < n_in; i++) {
        if      (in_sizes[i] == B_ * T_ * NIN) x = (const float*)d_in[i];
        else if (in_sizes[i] == NOUT)          s = (const float*)d_in[i];
        else if (in_sizes[i] == NIN * NOUT)    m = (const float*)d_in[i];
    }
    float* out = (float*)d_out;

    const int smem_bytes =
        (TILE_T * XS_LD + NOUT * MS_LD) * (int)sizeof(float)
        + TILE_T * WS2_LD * (int)sizeof(u64)
        + (TILE_T + 2 * NOUT) * (int)sizeof(float);   // ~170 KB

    cudaFuncSetAttribute(lde_phase1,
                         cudaFuncAttributeMaxDynamicSharedMemorySize, smem_bytes);

    lde_phase1<<<dim3(CHUNKS, B_), 256, smem_bytes>>>(x, s, m);
    lde_phase2<<<(B_ * NOUT * NIN) / (256 * 4), 256>>>(m, out);
}